// round 1
// baseline (speedup 1.0000x reference)
#include <cuda_runtime.h>
#include <math.h>

// Problem constants
#define GXN 128
#define GYN 128
#define NA 9
#define NCELLS (32 * 128 * 128)   // 524288
#define CPB 256                    // cells per block
#define TPB 256                    // threads per block
#define NBLOCKS (NCELLS / CPB)     // 2048

// Global accumulators: allloss, jbb, huhuh, zsd, pos_count
__device__ double g_acc[5];

__global__ void zero_acc_kernel() {
    int i = threadIdx.x;
    if (i < 5) g_acc[i] = 0.0;
}

__global__ __launch_bounds__(TPB) void loss_kernel(
    const float* __restrict__ out,
    const float* __restrict__ target)
{
    __shared__ float s_out[CPB * 45];          // 46080 bytes
    __shared__ float s_red[8][5];              // warp partials

    const int tid = threadIdx.x;
    const int blockBase = blockIdx.x * CPB;    // first cell of this block

    // ---- Stage this block's `out` slice coalesced (float4) ----
    {
        const float4* src = reinterpret_cast<const float4*>(out + (size_t)blockBase * 45);
        float4* dst = reinterpret_cast<float4*>(s_out);
        #pragma unroll 4
        for (int i = tid; i < (CPB * 45) / 4; i += TPB)
            dst[i] = src[i];
    }
    __syncthreads();

    const int cell = blockBase + tid;
    const int gy = cell & 127;
    const int gx = (cell >> 7) & 127;

    // ---- Load target[cell, 0, :] ----
    const float* st = target + (size_t)cell * 18;
    const float st0 = __ldg(st + 0);
    const float st1 = __ldg(st + 1);
    const float st2 = __ldg(st + 2);
    const float st3 = __ldg(st + 3);
    const float st5 = __ldg(st + 5);
    const bool pos = st5 > 0.8f;

    float acc_allloss = 0.0f;
    float acc_jbb = 0.0f;
    float acc_huhuh = 0.0f;
    float acc_zsd = 0.0f;

    const float* s = s_out + tid * 45;

    if (pos) {
        // A-box (loop invariant per cell)
        const float ax1 = st0 - st2 * 0.5f;
        const float ax2 = st0 + st2 * 0.5f;
        const float ay1 = st1 - st3 * 0.5f;
        const float ay2 = st1 + st3 * 0.5f;
        const float area_a = (ax2 - ax1) * (ay2 - ay1);
        const float atana = atanf((ax2 - ax1) / (ay2 - ay1));
        const float acx2 = ax1 + ax2;   // 2*center
        const float acy2 = ay1 + ay2;

        const float zx = (float)gx * (1.0f / GXN) + 1.0f / (2.0f * GXN);
        const float zy = (float)gy * (1.0f / GYN) + 1.0f / (2.0f * GYN);
        const float FOUR_OVER_PI2 = 4.0f / (3.14159265358979323846f * 3.14159265358979323846f);

        #pragma unroll
        for (int a = 0; a < NA; a++) {
            const float o0 = s[a * 5 + 0];
            const float o1 = s[a * 5 + 1];
            const float o2 = s[a * 5 + 2];
            const float o3 = s[a * 5 + 3];
            const float obj = s[a * 5 + 4];

            const float bcx = o0 - 0.5f + zx;
            const float bcy = o1 - 0.5f + zy;
            const float bw  = o2 - 0.5f + (1.0f / GXN);
            const float bh  = o3 - 0.5f + (1.0f / GYN);
            const float bx1 = bcx - bw * 0.5f;
            const float bx2 = bcx + bw * 0.5f;
            const float by1 = bcy - bh * 0.5f;
            const float by2 = bcy + bh * 0.5f;

            const float iw = fminf(ax2, bx2) - fmaxf(ax1, bx1);
            const float ih = fminf(ay2, by2) - fmaxf(ay1, by1);
            const float cross = (iw > 0.0f && ih > 0.0f) ? iw * ih : 0.0f;
            const float area_b = (bx2 - bx1) * (by2 - by1);
            const float uni = area_a + area_b - cross;
            const float iou = cross / (uni + 1e-6f);

            const float dx = (bx1 + bx2) * 0.5f - acx2 * 0.5f;
            const float dy = (by1 + by2) * 0.5f - acy2 * 0.5f;
            const float d2 = dx * dx + dy * dy;

            const float cx1 = fminf(ax1, bx1);
            const float cy1 = fminf(ay1, by1);
            const float cx2 = fmaxf(ax2, bx2);
            const float cy2 = fmaxf(ay2, by2);
            const float cw = cx2 - cx1;
            const float ch = cy2 - cy1;
            const float c2 = cw * cw + ch * ch;

            const float diou = iou - d2 / c2;

            const float da = atana - atanf((bx2 - bx1) / (by2 - by1));
            const float v = FOUR_OVER_PI2 * da * da;
            const float alpha = v / (1.0f - iou + v);
            const float los = 1.0f - (diou - alpha * v);

            const float om = 1.0f - obj;
            acc_allloss += los + om;
            acc_jbb += iou;
            acc_huhuh += om;
            acc_zsd += om * om;
        }
    } else {
        #pragma unroll
        for (int a = 0; a < NA; a++) {
            const float obj = s[a * 5 + 4];
            acc_zsd += obj * obj;
        }
    }

    // ---- Reduce: 4 floats + pos count ----
    float vals[5];
    vals[0] = acc_allloss;
    vals[1] = acc_jbb;
    vals[2] = acc_huhuh;
    vals[3] = acc_zsd;
    vals[4] = pos ? 1.0f : 0.0f;

    const unsigned FULL = 0xFFFFFFFFu;
    #pragma unroll
    for (int k = 0; k < 5; k++) {
        float v = vals[k];
        v += __shfl_xor_sync(FULL, v, 16);
        v += __shfl_xor_sync(FULL, v, 8);
        v += __shfl_xor_sync(FULL, v, 4);
        v += __shfl_xor_sync(FULL, v, 2);
        v += __shfl_xor_sync(FULL, v, 1);
        vals[k] = v;
    }
    const int warp = tid >> 5;
    const int lane = tid & 31;
    if (lane == 0) {
        #pragma unroll
        for (int k = 0; k < 5; k++) s_red[warp][k] = vals[k];
    }
    __syncthreads();

    if (warp == 0 && lane < 5) {
        float v = 0.0f;
        #pragma unroll
        for (int w = 0; w < 8; w++) v += s_red[w][lane];
        atomicAdd(&g_acc[lane], (double)v);
    }
}

__global__ void finalize_kernel(float* __restrict__ o) {
    if (threadIdx.x == 0) {
        const double npos = g_acc[4];
        const double jsq = npos * (double)NA;
        const double qit = ((double)NCELLS - npos) * (double)NA;
        o[0] = (float)(g_acc[0] / jsq + g_acc[3] / (jsq + qit));
        o[1] = (float)(g_acc[1] / jsq);
        o[2] = (float)(g_acc[2] / jsq);
    }
}

extern "C" void kernel_launch(void* const* d_in, const int* in_sizes, int n_in,
                              void* d_out, int out_size) {
    const float* out_t = (const float*)d_in[0];
    const float* target = (const float*)d_in[1];
    float* o = (float*)d_out;

    zero_acc_kernel<<<1, 32>>>();
    loss_kernel<<<NBLOCKS, TPB>>>(out_t, target);
    finalize_kernel<<<1, 32>>>(o);
}

// round 2
// speedup vs baseline: 1.0632x; 1.0632x over previous
#include <cuda_runtime.h>
#include <math.h>

#define GXN 128
#define GYN 128
#define NA 9
#define NCELLS (32 * 128 * 128)   // 524288
#define CPB 256                    // cells per block
#define TPB 256                    // threads per block
#define NBLOCKS (NCELLS / CPB)     // 2048

// Global accumulators: allloss, jbb, huhuh, zsd, pos_count
__device__ double g_acc[5];
__device__ unsigned int g_count = 0;

__global__ __launch_bounds__(TPB) void loss_kernel(
    const float* __restrict__ out,
    const float* __restrict__ target,
    float* __restrict__ o)
{
    extern __shared__ float smem[];
    float* s_out = smem;                 // CPB*45 floats (46080 B)
    float* s_tgt = smem + CPB * 45;      // CPB*18 floats (18432 B)

    __shared__ unsigned short s_posidx[CPB];
    __shared__ int s_wcnt[8];
    __shared__ int s_wbase[9];
    __shared__ float s_red[8][5];
    __shared__ int s_islast;

    const int tid = threadIdx.x;
    const int blockBase = blockIdx.x * CPB;

    // ---- Stage out + target slices, fully coalesced float4 ----
    {
        const float4* src = reinterpret_cast<const float4*>(out + (size_t)blockBase * 45);
        float4* dst = reinterpret_cast<float4*>(s_out);
        #pragma unroll 4
        for (int i = tid; i < (CPB * 45) / 4; i += TPB)
            dst[i] = src[i];

        const float4* tsrc = reinterpret_cast<const float4*>(target + (size_t)blockBase * 18);
        float4* tdst = reinterpret_cast<float4*>(s_tgt);
        #pragma unroll 2
        for (int i = tid; i < (CPB * 18) / 4; i += TPB)
            tdst[i] = tsrc[i];
    }
    __syncthreads();

    // ---- Own cell: pos flag + cheap negative path ----
    const float st5 = s_tgt[tid * 18 + 5];
    const bool pos = st5 > 0.8f;

    float acc_zsd = 0.0f;
    if (!pos) {
        const float* s = s_out + tid * 45;
        #pragma unroll
        for (int a = 0; a < NA; a++) {
            const float obj = s[a * 5 + 4];
            acc_zsd += obj * obj;
        }
    }

    // ---- Compact pos cells within the block ----
    const unsigned FULL = 0xFFFFFFFFu;
    const int warp = tid >> 5;
    const int lane = tid & 31;
    const unsigned ballot = __ballot_sync(FULL, pos);
    if (lane == 0) s_wcnt[warp] = __popc(ballot);
    __syncthreads();
    if (tid == 0) {
        int run = 0;
        #pragma unroll
        for (int w = 0; w < 8; w++) { s_wbase[w] = run; run += s_wcnt[w]; }
        s_wbase[8] = run;
    }
    __syncthreads();
    if (pos) {
        const int off = s_wbase[warp] + __popc(ballot & ((1u << lane) - 1u));
        s_posidx[off] = (unsigned short)tid;
    }
    __syncthreads();
    const int nP = s_wbase[8];

    // ---- Heavy path on compacted pos cells (uniform warps) ----
    float acc_allloss = 0.0f;
    float acc_jbb = 0.0f;
    float acc_huhuh = 0.0f;

    if (tid < nP) {
        const int c = s_posidx[tid];
        const int cellc = blockBase + c;
        const int gy = cellc & 127;
        const int gx = (cellc >> 7) & 127;

        const float* st = s_tgt + c * 18;
        const float st0 = st[0];
        const float st1 = st[1];
        const float st2 = st[2];
        const float st3 = st[3];

        const float ax1 = st0 - st2 * 0.5f;
        const float ax2 = st0 + st2 * 0.5f;
        const float ay1 = st1 - st3 * 0.5f;
        const float ay2 = st1 + st3 * 0.5f;
        const float area_a = (ax2 - ax1) * (ay2 - ay1);
        const float atana = atanf(__fdividef(ax2 - ax1, ay2 - ay1));
        const float acx = (ax1 + ax2) * 0.5f;
        const float acy = (ay1 + ay2) * 0.5f;

        const float zx = (float)gx * (1.0f / GXN) + 1.0f / (2.0f * GXN);
        const float zy = (float)gy * (1.0f / GYN) + 1.0f / (2.0f * GYN);
        const float FOUR_OVER_PI2 = 4.0f / (3.14159265358979323846f * 3.14159265358979323846f);

        const float* s = s_out + c * 45;

        #pragma unroll
        for (int a = 0; a < NA; a++) {
            const float o0 = s[a * 5 + 0];
            const float o1 = s[a * 5 + 1];
            const float o2 = s[a * 5 + 2];
            const float o3 = s[a * 5 + 3];
            const float obj = s[a * 5 + 4];

            const float bcx = o0 - 0.5f + zx;
            const float bcy = o1 - 0.5f + zy;
            const float bw  = o2 - 0.5f + (1.0f / GXN);
            const float bh  = o3 - 0.5f + (1.0f / GYN);
            const float bx1 = bcx - bw * 0.5f;
            const float bx2 = bcx + bw * 0.5f;
            const float by1 = bcy - bh * 0.5f;
            const float by2 = bcy + bh * 0.5f;

            const float iw = fminf(ax2, bx2) - fmaxf(ax1, bx1);
            const float ih = fminf(ay2, by2) - fmaxf(ay1, by1);
            const float cross = (iw > 0.0f && ih > 0.0f) ? iw * ih : 0.0f;
            const float area_b = (bx2 - bx1) * (by2 - by1);
            const float uni = area_a + area_b - cross;
            const float iou = __fdividef(cross, uni + 1e-6f);

            const float dx = bcx - acx;
            const float dy = bcy - acy;
            const float d2 = dx * dx + dy * dy;

            const float cw = fmaxf(ax2, bx2) - fminf(ax1, bx1);
            const float ch = fmaxf(ay2, by2) - fminf(ay1, by1);
            const float c2 = cw * cw + ch * ch;

            const float diou = iou - __fdividef(d2, c2);

            const float da = atana - atanf(__fdividef(bx2 - bx1, by2 - by1));
            const float v = FOUR_OVER_PI2 * da * da;
            const float alpha = __fdividef(v, 1.0f - iou + v);
            const float los = 1.0f - (diou - alpha * v);

            const float om = 1.0f - obj;
            acc_allloss += los + om;
            acc_jbb += iou;
            acc_huhuh += om;
            acc_zsd += om * om;
        }
    }

    // ---- Block reduction: 4 sums + pos count ----
    float vals[5];
    vals[0] = acc_allloss;
    vals[1] = acc_jbb;
    vals[2] = acc_huhuh;
    vals[3] = acc_zsd;
    vals[4] = pos ? 1.0f : 0.0f;

    #pragma unroll
    for (int k = 0; k < 5; k++) {
        float v = vals[k];
        v += __shfl_xor_sync(FULL, v, 16);
        v += __shfl_xor_sync(FULL, v, 8);
        v += __shfl_xor_sync(FULL, v, 4);
        v += __shfl_xor_sync(FULL, v, 2);
        v += __shfl_xor_sync(FULL, v, 1);
        vals[k] = v;
    }
    if (lane == 0) {
        #pragma unroll
        for (int k = 0; k < 5; k++) s_red[warp][k] = vals[k];
    }
    __syncthreads();

    if (warp == 0 && lane < 5) {
        float v = 0.0f;
        #pragma unroll
        for (int w = 0; w < 8; w++) v += s_red[w][lane];
        atomicAdd(&g_acc[lane], (double)v);
    }
    __syncthreads();

    // ---- Last block finalizes and resets for next graph replay ----
    if (tid == 0) {
        __threadfence();
        const unsigned done = atomicAdd(&g_count, 1u);
        s_islast = (done == (unsigned)(gridDim.x - 1)) ? 1 : 0;
    }
    __syncthreads();

    if (s_islast && tid == 0) {
        // atomic reads ensure visibility of all blocks' contributions
        const double a0 = atomicAdd(&g_acc[0], 0.0);
        const double a1 = atomicAdd(&g_acc[1], 0.0);
        const double a2 = atomicAdd(&g_acc[2], 0.0);
        const double a3 = atomicAdd(&g_acc[3], 0.0);
        const double npos = atomicAdd(&g_acc[4], 0.0);

        const double jsq = npos * (double)NA;
        const double qit = ((double)NCELLS - npos) * (double)NA;
        o[0] = (float)(a0 / jsq + a3 / (jsq + qit));
        o[1] = (float)(a1 / jsq);
        o[2] = (float)(a2 / jsq);

        // reset for next replay
        g_acc[0] = 0.0; g_acc[1] = 0.0; g_acc[2] = 0.0;
        g_acc[3] = 0.0; g_acc[4] = 0.0;
        __threadfence();
        g_count = 0u;
    }
}

extern "C" void kernel_launch(void* const* d_in, const int* in_sizes, int n_in,
                              void* d_out, int out_size) {
    const float* out_t = (const float*)d_in[0];
    const float* target = (const float*)d_in[1];
    float* o = (float*)d_out;

    const int smem_bytes = (CPB * 45 + CPB * 18) * (int)sizeof(float); // 64512
    static int configured = 0;
    if (!configured) {
        cudaFuncSetAttribute(loss_kernel,
                             cudaFuncAttributeMaxDynamicSharedMemorySize,
                             smem_bytes);
        configured = 1;
    }
    loss_kernel<<<NBLOCKS, TPB, smem_bytes>>>(out_t, target, o);
}

// round 3
// speedup vs baseline: 1.2885x; 1.2119x over previous
#include <cuda_runtime.h>
#include <math.h>

#define GXN 128
#define GYN 128
#define NA 9
#define NCELLS (32 * 128 * 128)   // 524288
#define CPB 128                    // cells per block
#define TPB 128                    // threads per block
#define NBLOCKS (NCELLS / CPB)     // 4096
#define NWARPS (TPB / 32)          // 4

// Global accumulators: allloss, jbb, huhuh, zsd, pos_count
__device__ double g_acc[5];
__device__ unsigned int g_count = 0;

__global__ __launch_bounds__(TPB) void loss_kernel(
    const float* __restrict__ out,
    const float* __restrict__ target,
    float* __restrict__ o)
{
    extern __shared__ float s_out[];           // CPB*45 floats = 23040 B

    __shared__ unsigned short s_posidx[CPB];
    __shared__ int s_wcnt[NWARPS];
    __shared__ int s_wbase[NWARPS + 1];
    __shared__ float s_red[NWARPS][5];
    __shared__ int s_islast;

    const int tid = threadIdx.x;
    const int blockBase = blockIdx.x * CPB;
    const int cell = blockBase + tid;

    // ---- Early target load (overlaps with staging) ----
    const float st5 = __ldg(target + (size_t)cell * 18 + 5);

    // ---- Stage this block's `out` slice, coalesced float4 ----
    {
        const float4* src = reinterpret_cast<const float4*>(out + (size_t)blockBase * 45);
        float4* dst = reinterpret_cast<float4*>(s_out);
        #pragma unroll
        for (int i = tid; i < (CPB * 45) / 4; i += TPB)
            dst[i] = src[i];
    }

    const bool pos = st5 > 0.8f;

    // ---- Compact pos cells within the block (overlaps with staging latency) ----
    const unsigned FULL = 0xFFFFFFFFu;
    const int warp = tid >> 5;
    const int lane = tid & 31;
    const unsigned ballot = __ballot_sync(FULL, pos);
    if (lane == 0) s_wcnt[warp] = __popc(ballot);
    __syncthreads();   // covers staging + wcnt
    if (tid == 0) {
        int run = 0;
        #pragma unroll
        for (int w = 0; w < NWARPS; w++) { s_wbase[w] = run; run += s_wcnt[w]; }
        s_wbase[NWARPS] = run;
    }
    __syncthreads();
    if (pos) {
        const int off = s_wbase[warp] + __popc(ballot & ((1u << lane) - 1u));
        s_posidx[off] = (unsigned short)tid;
    }
    __syncthreads();
    const int nP = s_wbase[NWARPS];

    // ---- Cheap negative path on own cell ----
    float acc_zsd = 0.0f;
    if (!pos) {
        const float* s = s_out + tid * 45;
        #pragma unroll
        for (int a = 0; a < NA; a++) {
            const float obj = s[a * 5 + 4];
            acc_zsd += obj * obj;
        }
    }

    // ---- Heavy path on compacted pos cells ----
    float acc_allloss = 0.0f;
    float acc_jbb = 0.0f;
    float acc_huhuh = 0.0f;

    if (tid < nP) {
        const int c = s_posidx[tid];
        const int cellc = blockBase + c;
        const int gy = cellc & 127;
        const int gx = (cellc >> 7) & 127;

        const float* st = target + (size_t)cellc * 18;
        const float st0 = __ldg(st + 0);
        const float st1 = __ldg(st + 1);
        const float st2 = __ldg(st + 2);
        const float st3 = __ldg(st + 3);

        const float ax1 = st0 - st2 * 0.5f;
        const float ax2 = st0 + st2 * 0.5f;
        const float ay1 = st1 - st3 * 0.5f;
        const float ay2 = st1 + st3 * 0.5f;
        const float area_a = (ax2 - ax1) * (ay2 - ay1);
        const float atana = atanf(__fdividef(ax2 - ax1, ay2 - ay1));
        const float acx = (ax1 + ax2) * 0.5f;
        const float acy = (ay1 + ay2) * 0.5f;

        const float zx = (float)gx * (1.0f / GXN) + 1.0f / (2.0f * GXN);
        const float zy = (float)gy * (1.0f / GYN) + 1.0f / (2.0f * GYN);
        const float FOUR_OVER_PI2 = 4.0f / (3.14159265358979323846f * 3.14159265358979323846f);

        const float* s = s_out + c * 45;

        #pragma unroll
        for (int a = 0; a < NA; a++) {
            const float o0 = s[a * 5 + 0];
            const float o1 = s[a * 5 + 1];
            const float o2 = s[a * 5 + 2];
            const float o3 = s[a * 5 + 3];
            const float obj = s[a * 5 + 4];

            const float bcx = o0 - 0.5f + zx;
            const float bcy = o1 - 0.5f + zy;
            const float bw  = o2 - 0.5f + (1.0f / GXN);
            const float bh  = o3 - 0.5f + (1.0f / GYN);
            const float bx1 = bcx - bw * 0.5f;
            const float bx2 = bcx + bw * 0.5f;
            const float by1 = bcy - bh * 0.5f;
            const float by2 = bcy + bh * 0.5f;

            const float iw = fminf(ax2, bx2) - fmaxf(ax1, bx1);
            const float ih = fminf(ay2, by2) - fmaxf(ay1, by1);
            const float cross = (iw > 0.0f && ih > 0.0f) ? iw * ih : 0.0f;
            const float area_b = (bx2 - bx1) * (by2 - by1);
            const float uni = area_a + area_b - cross;
            const float iou = __fdividef(cross, uni + 1e-6f);

            const float dx = bcx - acx;
            const float dy = bcy - acy;
            const float d2 = dx * dx + dy * dy;

            const float cw = fmaxf(ax2, bx2) - fminf(ax1, bx1);
            const float ch = fmaxf(ay2, by2) - fminf(ay1, by1);
            const float c2 = cw * cw + ch * ch;

            const float diou = iou - __fdividef(d2, c2);

            const float da = atana - atanf(__fdividef(bx2 - bx1, by2 - by1));
            const float v = FOUR_OVER_PI2 * da * da;
            const float alpha = __fdividef(v, 1.0f - iou + v);
            const float los = 1.0f - (diou - alpha * v);

            const float om = 1.0f - obj;
            acc_allloss += los + om;
            acc_jbb += iou;
            acc_huhuh += om;
            acc_zsd += om * om;
        }
    }

    // ---- Block reduction: 4 sums + pos count ----
    float vals[5];
    vals[0] = acc_allloss;
    vals[1] = acc_jbb;
    vals[2] = acc_huhuh;
    vals[3] = acc_zsd;
    vals[4] = pos ? 1.0f : 0.0f;

    #pragma unroll
    for (int k = 0; k < 5; k++) {
        float v = vals[k];
        v += __shfl_xor_sync(FULL, v, 16);
        v += __shfl_xor_sync(FULL, v, 8);
        v += __shfl_xor_sync(FULL, v, 4);
        v += __shfl_xor_sync(FULL, v, 2);
        v += __shfl_xor_sync(FULL, v, 1);
        vals[k] = v;
    }
    if (lane == 0) {
        #pragma unroll
        for (int k = 0; k < 5; k++) s_red[warp][k] = vals[k];
    }
    __syncthreads();

    if (warp == 0 && lane < 5) {
        float v = 0.0f;
        #pragma unroll
        for (int w = 0; w < NWARPS; w++) v += s_red[w][lane];
        atomicAdd(&g_acc[lane], (double)v);
    }
    __syncthreads();

    // ---- Last block finalizes and resets for next graph replay ----
    if (tid == 0) {
        __threadfence();
        const unsigned done = atomicAdd(&g_count, 1u);
        s_islast = (done == (unsigned)(gridDim.x - 1)) ? 1 : 0;
    }
    __syncthreads();

    if (s_islast && tid == 0) {
        const double a0 = atomicAdd(&g_acc[0], 0.0);
        const double a1 = atomicAdd(&g_acc[1], 0.0);
        const double a2 = atomicAdd(&g_acc[2], 0.0);
        const double a3 = atomicAdd(&g_acc[3], 0.0);
        const double npos = atomicAdd(&g_acc[4], 0.0);

        const double jsq = npos * (double)NA;
        const double qit = ((double)NCELLS - npos) * (double)NA;
        o[0] = (float)(a0 / jsq + a3 / (jsq + qit));
        o[1] = (float)(a1 / jsq);
        o[2] = (float)(a2 / jsq);

        g_acc[0] = 0.0; g_acc[1] = 0.0; g_acc[2] = 0.0;
        g_acc[3] = 0.0; g_acc[4] = 0.0;
        __threadfence();
        g_count = 0u;
    }
}

extern "C" void kernel_launch(void* const* d_in, const int* in_sizes, int n_in,
                              void* d_out, int out_size) {
    const float* out_t = (const float*)d_in[0];
    const float* target = (const float*)d_in[1];
    float* o = (float*)d_out;

    const int smem_bytes = CPB * 45 * (int)sizeof(float); // 23040
    static int configured = 0;
    if (!configured) {
        cudaFuncSetAttribute(loss_kernel,
                             cudaFuncAttributeMaxDynamicSharedMemorySize,
                             smem_bytes);
        configured = 1;
    }
    loss_kernel<<<NBLOCKS, TPB, smem_bytes>>>(out_t, target, o);
}

// round 4
// speedup vs baseline: 1.3578x; 1.0538x over previous
#include <cuda_runtime.h>
#include <math.h>

#define GXN 128
#define GYN 128
#define NA 9
#define NCELLS (32 * 128 * 128)    // 524288
#define CPB 128                     // cells per tile
#define TPB 128                     // threads per block
#define TILES 4                     // tiles per block
#define NBLOCKS (NCELLS / (CPB * TILES))  // 1024
#define NWARPS (TPB / 32)           // 4
#define TILE_F4 ((CPB * 45) / 4)    // 1440 float4 per tile
#define TILE_FLOATS (CPB * 45)      // 5760

__device__ double g_acc[5];
__device__ unsigned int g_count = 0;

__device__ __forceinline__ unsigned smem_u32(const void* p) {
    return (unsigned)__cvta_generic_to_shared(p);
}
#define CP_ASYNC_16(dst_u32, src_ptr) \
    asm volatile("cp.async.cg.shared.global [%0], [%1], 16;" :: "r"(dst_u32), "l"(src_ptr))
#define CP_COMMIT() asm volatile("cp.async.commit_group;")
#define CP_WAIT(n)  asm volatile("cp.async.wait_group %0;" :: "n"(n))

__device__ __forceinline__ void stage_tile(const float* __restrict__ out,
                                           int tileCellBase, float* buf, int tid)
{
    const float4* src = reinterpret_cast<const float4*>(out + (size_t)tileCellBase * 45);
    const unsigned dst = smem_u32(buf);
    // 1440 = 11*128 + 32
    #pragma unroll
    for (int k = 0; k < 11; k++) {
        const int idx = tid + k * TPB;
        CP_ASYNC_16(dst + idx * 16, src + idx);
    }
    if (tid < 32) {
        const int idx = tid + 11 * TPB;
        CP_ASYNC_16(dst + idx * 16, src + idx);
    }
}

__global__ __launch_bounds__(TPB) void loss_kernel(
    const float* __restrict__ out,
    const float* __restrict__ target,
    float* __restrict__ o)
{
    extern __shared__ float s_buf[];            // 2 * TILE_FLOATS floats = 46080 B

    __shared__ unsigned s_ballot[NWARPS];
    __shared__ unsigned short s_posidx[CPB];
    __shared__ float s_red[NWARPS][5];
    __shared__ int s_islast;

    const int tid = threadIdx.x;
    const int warp = tid >> 5;
    const int lane = tid & 31;
    const unsigned FULL = 0xFFFFFFFFu;
    const unsigned lanemask_lt = (1u << lane) - 1u;
    const int blockBase = blockIdx.x * (CPB * TILES);

    // ---- Prologue: launch copies for tiles 0 and 1; prefetch st5 of tile 0 ----
    stage_tile(out, blockBase + 0 * CPB, s_buf, tid);
    CP_COMMIT();
    stage_tile(out, blockBase + 1 * CPB, s_buf + TILE_FLOATS, tid);
    CP_COMMIT();
    float st5_cur = __ldg(target + (size_t)(blockBase + tid) * 18 + 5);

    float acc_allloss = 0.0f;
    float acc_jbb = 0.0f;
    float acc_huhuh = 0.0f;
    float acc_zsd = 0.0f;
    float acc_npos = 0.0f;

    #pragma unroll
    for (int t = 0; t < TILES; t++) {
        const int tileBase = blockBase + t * CPB;
        float* buf = s_buf + (t & 1) * TILE_FLOATS;

        // Prefetch st5 for next tile (issued before the wait → overlaps)
        float st5_next = 0.0f;
        if (t + 1 < TILES)
            st5_next = __ldg(target + (size_t)(tileBase + CPB + tid) * 18 + 5);

        // Wait for tile t's copy (keep the next tile's copy in flight)
        if (t == TILES - 1) { CP_WAIT(0); } else { CP_WAIT(1); }

        const bool pos = st5_cur > 0.8f;
        const unsigned ballot = __ballot_sync(FULL, pos);
        if (lane == 0) s_ballot[warp] = ballot;
        __syncthreads();   // A: tile data + ballots visible to all

        int base = 0, nP = 0;
        #pragma unroll
        for (int w = 0; w < NWARPS; w++) {
            const int c = __popc(s_ballot[w]);
            if (w < warp) base += c;
            nP += c;
        }
        if (pos) {
            s_posidx[base + __popc(ballot & lanemask_lt)] = (unsigned short)tid;
            acc_npos += 1.0f;
        } else {
            // cheap negative path (only needs data ready at A)
            const float* s = buf + tid * 45;
            #pragma unroll
            for (int a = 0; a < NA; a++) {
                const float obj = s[a * 5 + 4];
                acc_zsd += obj * obj;
            }
        }
        __syncthreads();   // B: posidx visible

        if (tid < nP) {
            const int c = s_posidx[tid];
            const int cellc = tileBase + c;
            const int gy = cellc & 127;
            const int gx = (cellc >> 7) & 127;

            const float* st = target + (size_t)cellc * 18;
            const float st0 = __ldg(st + 0);
            const float st1 = __ldg(st + 1);
            const float st2 = __ldg(st + 2);
            const float st3 = __ldg(st + 3);

            const float ax1 = st0 - st2 * 0.5f;
            const float ax2 = st0 + st2 * 0.5f;
            const float ay1 = st1 - st3 * 0.5f;
            const float ay2 = st1 + st3 * 0.5f;
            const float area_a = (ax2 - ax1) * (ay2 - ay1);
            const float atana = atanf(__fdividef(ax2 - ax1, ay2 - ay1));
            const float acx = (ax1 + ax2) * 0.5f;
            const float acy = (ay1 + ay2) * 0.5f;

            const float zx = (float)gx * (1.0f / GXN) + 1.0f / (2.0f * GXN);
            const float zy = (float)gy * (1.0f / GYN) + 1.0f / (2.0f * GYN);
            const float FOUR_OVER_PI2 =
                4.0f / (3.14159265358979323846f * 3.14159265358979323846f);

            const float* s = buf + c * 45;

            #pragma unroll
            for (int a = 0; a < NA; a++) {
                const float o0 = s[a * 5 + 0];
                const float o1 = s[a * 5 + 1];
                const float o2 = s[a * 5 + 2];
                const float o3 = s[a * 5 + 3];
                const float obj = s[a * 5 + 4];

                const float bcx = o0 - 0.5f + zx;
                const float bcy = o1 - 0.5f + zy;
                const float bw  = o2 - 0.5f + (1.0f / GXN);
                const float bh  = o3 - 0.5f + (1.0f / GYN);
                const float bx1 = bcx - bw * 0.5f;
                const float bx2 = bcx + bw * 0.5f;
                const float by1 = bcy - bh * 0.5f;
                const float by2 = bcy + bh * 0.5f;

                const float iw = fminf(ax2, bx2) - fmaxf(ax1, bx1);
                const float ih = fminf(ay2, by2) - fmaxf(ay1, by1);
                const float cross = (iw > 0.0f && ih > 0.0f) ? iw * ih : 0.0f;
                const float area_b = (bx2 - bx1) * (by2 - by1);
                const float uni = area_a + area_b - cross;
                const float iou = __fdividef(cross, uni + 1e-6f);

                const float dx = bcx - acx;
                const float dy = bcy - acy;
                const float d2 = dx * dx + dy * dy;

                const float cw = fmaxf(ax2, bx2) - fminf(ax1, bx1);
                const float ch = fmaxf(ay2, by2) - fminf(ay1, by1);
                const float c2 = cw * cw + ch * ch;

                const float diou = iou - __fdividef(d2, c2);

                const float da = atana - atanf(__fdividef(bx2 - bx1, by2 - by1));
                const float v = FOUR_OVER_PI2 * da * da;
                const float alpha = __fdividef(v, 1.0f - iou + v);
                const float los = 1.0f - (diou - alpha * v);

                const float om = 1.0f - obj;
                acc_allloss += los + om;
                acc_jbb += iou;
                acc_huhuh += om;
                acc_zsd += om * om;
            }
        }
        __syncthreads();   // C: buffer free for reuse

        if (t + 2 < TILES) {
            stage_tile(out, blockBase + (t + 2) * CPB, buf, tid);
        }
        CP_COMMIT();       // commit (possibly empty group keeps the count schedule)

        st5_cur = st5_next;
    }

    // ---- Block reduction: 4 sums + pos count ----
    float vals[5];
    vals[0] = acc_allloss;
    vals[1] = acc_jbb;
    vals[2] = acc_huhuh;
    vals[3] = acc_zsd;
    vals[4] = acc_npos;

    #pragma unroll
    for (int k = 0; k < 5; k++) {
        float v = vals[k];
        v += __shfl_xor_sync(FULL, v, 16);
        v += __shfl_xor_sync(FULL, v, 8);
        v += __shfl_xor_sync(FULL, v, 4);
        v += __shfl_xor_sync(FULL, v, 2);
        v += __shfl_xor_sync(FULL, v, 1);
        vals[k] = v;
    }
    if (lane == 0) {
        #pragma unroll
        for (int k = 0; k < 5; k++) s_red[warp][k] = vals[k];
    }
    __syncthreads();

    if (warp == 0 && lane < 5) {
        float v = 0.0f;
        #pragma unroll
        for (int w = 0; w < NWARPS; w++) v += s_red[w][lane];
        atomicAdd(&g_acc[lane], (double)v);
    }
    __syncthreads();

    // ---- Last block finalizes and resets for next graph replay ----
    if (tid == 0) {
        __threadfence();
        const unsigned done = atomicAdd(&g_count, 1u);
        s_islast = (done == (unsigned)(gridDim.x - 1)) ? 1 : 0;
    }
    __syncthreads();

    if (s_islast && tid == 0) {
        const double a0 = atomicAdd(&g_acc[0], 0.0);
        const double a1 = atomicAdd(&g_acc[1], 0.0);
        const double a2 = atomicAdd(&g_acc[2], 0.0);
        const double a3 = atomicAdd(&g_acc[3], 0.0);
        const double npos = atomicAdd(&g_acc[4], 0.0);

        const double jsq = npos * (double)NA;
        const double qit = ((double)NCELLS - npos) * (double)NA;
        o[0] = (float)(a0 / jsq + a3 / (jsq + qit));
        o[1] = (float)(a1 / jsq);
        o[2] = (float)(a2 / jsq);

        g_acc[0] = 0.0; g_acc[1] = 0.0; g_acc[2] = 0.0;
        g_acc[3] = 0.0; g_acc[4] = 0.0;
        __threadfence();
        g_count = 0u;
    }
}

extern "C" void kernel_launch(void* const* d_in, const int* in_sizes, int n_in,
                              void* d_out, int out_size) {
    const float* out_t = (const float*)d_in[0];
    const float* target = (const float*)d_in[1];
    float* o = (float*)d_out;

    const int smem_bytes = 2 * TILE_FLOATS * (int)sizeof(float); // 46080
    static int configured = 0;
    if (!configured) {
        cudaFuncSetAttribute(loss_kernel,
                             cudaFuncAttributeMaxDynamicSharedMemorySize,
                             smem_bytes);
        configured = 1;
    }
    loss_kernel<<<NBLOCKS, TPB, smem_bytes>>>(out_t, target, o);
}

// round 5
// speedup vs baseline: 1.3627x; 1.0036x over previous
#include <cuda_runtime.h>
#include <math.h>

#define GXN 128
#define GYN 128
#define NA 9
#define NCELLS (32 * 128 * 128)        // 524288
#define TPB 128
#define NWARPS (TPB / 32)              // 4
#define CHUNK 16                        // cells per warp-chunk
#define CHUNKS 8                        // chunks per warp
#define WARP_CELLS (CHUNK * CHUNKS)     // 128
#define BLOCK_CELLS (WARP_CELLS * NWARPS) // 512
#define NBLOCKS (NCELLS / BLOCK_CELLS)  // 1024
#define CHUNK_FLOATS (CHUNK * 45)       // 720
#define CHUNK_F4 (CHUNK_FLOATS / 4)     // 180

__device__ double g_acc[5];
__device__ unsigned int g_count = 0;

__device__ __forceinline__ unsigned smem_u32(const void* p) {
    return (unsigned)__cvta_generic_to_shared(p);
}
#define CP_ASYNC_16(dst_u32, src_ptr) \
    asm volatile("cp.async.cg.shared.global [%0], [%1], 16;" :: "r"(dst_u32), "l"(src_ptr))
#define CP_COMMIT() asm volatile("cp.async.commit_group;")
#define CP_WAIT(n)  asm volatile("cp.async.wait_group %0;" :: "n"(n))

// Stage one 16-cell chunk (720 floats = 180 float4) with one warp.
__device__ __forceinline__ void stage_chunk(const float* __restrict__ out,
                                            int cellBase, float* buf, int lane)
{
    const float4* src = reinterpret_cast<const float4*>(out + (size_t)cellBase * 45);
    const unsigned dst = smem_u32(buf);
    #pragma unroll
    for (int r = 0; r < 5; r++) {
        const int idx = lane + r * 32;
        CP_ASYNC_16(dst + idx * 16, src + idx);
    }
    {
        const int idx = lane + 160;                 // 180 = 5*32 + 20
        if (idx < CHUNK_F4) CP_ASYNC_16(dst + idx * 16, src + idx);
    }
}

__global__ __launch_bounds__(TPB) void loss_kernel(
    const float* __restrict__ out,
    const float* __restrict__ target,
    float* __restrict__ o)
{
    extern __shared__ float s_buf[];    // NWARPS * 2 * 720 floats = 23040 B

    __shared__ float s_red[NWARPS][5];
    __shared__ int s_islast;

    const int tid = threadIdx.x;
    const int warp = tid >> 5;
    const int lane = tid & 31;
    const int c = lane & 15;            // cell within chunk
    const int half = lane >> 4;         // 0: anchors 0..4, 1: anchors 5..8
    const unsigned FULL = 0xFFFFFFFFu;

    const int warpBase = blockIdx.x * BLOCK_CELLS + warp * WARP_CELLS;
    float* wbuf = s_buf + warp * (2 * CHUNK_FLOATS);

    // ---- Prologue: stage chunks 0,1; prefetch st5 of chunk 0 ----
    stage_chunk(out, warpBase + 0 * CHUNK, wbuf, lane);
    CP_COMMIT();
    stage_chunk(out, warpBase + 1 * CHUNK, wbuf + CHUNK_FLOATS, lane);
    CP_COMMIT();
    float st5_cur = __ldg(target + (size_t)(warpBase + c) * 18 + 5);

    float acc_allloss = 0.0f;
    float acc_jbb = 0.0f;
    float acc_huhuh = 0.0f;
    float acc_zsd = 0.0f;
    float acc_npos = 0.0f;

    const float FOUR_OVER_PI2 = 4.0f / (3.14159265358979323846f * 3.14159265358979323846f);

    #pragma unroll
    for (int k = 0; k < CHUNKS; k++) {
        const int chunkBase = warpBase + k * CHUNK;
        float* buf = wbuf + (k & 1) * CHUNK_FLOATS;

        // Prefetch next chunk's st5 before blocking on the copy
        float st5_next = 0.0f;
        if (k + 1 < CHUNKS)
            st5_next = __ldg(target + (size_t)(chunkBase + CHUNK + c) * 18 + 5);

        if (k == CHUNKS - 1) { CP_WAIT(0); } else { CP_WAIT(1); }
        __syncwarp();

        const bool pos = st5_cur > 0.8f;
        const float* s = buf + c * 45;
        const int aBeg = half ? 5 : 0;

        if (!pos) {
            // negative path: obj^2 over this half's anchors
            #pragma unroll
            for (int j = 0; j < 5; j++) {
                if (j < 4 || !half) {
                    const float obj = s[(aBeg + j) * 5 + 4];
                    acc_zsd += obj * obj;
                }
            }
        } else {
            if (!half) acc_npos += 1.0f;

            const int cellc = chunkBase + c;
            const int gy = cellc & 127;
            const int gx = (cellc >> 7) & 127;

            const float* st = target + (size_t)cellc * 18;
            const float st0 = __ldg(st + 0);
            const float st1 = __ldg(st + 1);
            const float st2 = __ldg(st + 2);
            const float st3 = __ldg(st + 3);

            const float ax1 = st0 - st2 * 0.5f;
            const float ax2 = st0 + st2 * 0.5f;
            const float ay1 = st1 - st3 * 0.5f;
            const float ay2 = st1 + st3 * 0.5f;
            const float area_a = (ax2 - ax1) * (ay2 - ay1);
            const float atana = atanf(__fdividef(ax2 - ax1, ay2 - ay1));
            const float acx = (ax1 + ax2) * 0.5f;
            const float acy = (ay1 + ay2) * 0.5f;

            const float zx = (float)gx * (1.0f / GXN) + 1.0f / (2.0f * GXN);
            const float zy = (float)gy * (1.0f / GYN) + 1.0f / (2.0f * GYN);

            #pragma unroll
            for (int j = 0; j < 5; j++) {
                if (j < 4 || !half) {
                    const int a = aBeg + j;
                    const float o0 = s[a * 5 + 0];
                    const float o1 = s[a * 5 + 1];
                    const float o2 = s[a * 5 + 2];
                    const float o3 = s[a * 5 + 3];
                    const float obj = s[a * 5 + 4];

                    const float bcx = o0 - 0.5f + zx;
                    const float bcy = o1 - 0.5f + zy;
                    const float bw  = o2 - 0.5f + (1.0f / GXN);
                    const float bh  = o3 - 0.5f + (1.0f / GYN);
                    const float bx1 = bcx - bw * 0.5f;
                    const float bx2 = bcx + bw * 0.5f;
                    const float by1 = bcy - bh * 0.5f;
                    const float by2 = bcy + bh * 0.5f;

                    const float iw = fminf(ax2, bx2) - fmaxf(ax1, bx1);
                    const float ih = fminf(ay2, by2) - fmaxf(ay1, by1);
                    const float cross = (iw > 0.0f && ih > 0.0f) ? iw * ih : 0.0f;
                    const float area_b = (bx2 - bx1) * (by2 - by1);
                    const float uni = area_a + area_b - cross;
                    const float iou = __fdividef(cross, uni + 1e-6f);

                    const float dx = bcx - acx;
                    const float dy = bcy - acy;
                    const float d2 = dx * dx + dy * dy;

                    const float cw = fmaxf(ax2, bx2) - fminf(ax1, bx1);
                    const float ch = fmaxf(ay2, by2) - fminf(ay1, by1);
                    const float c2 = cw * cw + ch * ch;

                    const float diou = iou - __fdividef(d2, c2);

                    const float da = atana - atanf(__fdividef(bx2 - bx1, by2 - by1));
                    const float v = FOUR_OVER_PI2 * da * da;
                    const float alpha = __fdividef(v, 1.0f - iou + v);
                    const float los = 1.0f - (diou - alpha * v);

                    const float om = 1.0f - obj;
                    acc_allloss += los + om;
                    acc_jbb += iou;
                    acc_huhuh += om;
                    acc_zsd += om * om;
                }
            }
        }
        __syncwarp();   // buffer free for reuse

        if (k + 2 < CHUNKS)
            stage_chunk(out, warpBase + (k + 2) * CHUNK, buf, lane);
        CP_COMMIT();

        st5_cur = st5_next;
    }

    // ---- Block reduction: 4 sums + pos count ----
    float vals[5];
    vals[0] = acc_allloss;
    vals[1] = acc_jbb;
    vals[2] = acc_huhuh;
    vals[3] = acc_zsd;
    vals[4] = acc_npos;

    #pragma unroll
    for (int kk = 0; kk < 5; kk++) {
        float v = vals[kk];
        v += __shfl_xor_sync(FULL, v, 16);
        v += __shfl_xor_sync(FULL, v, 8);
        v += __shfl_xor_sync(FULL, v, 4);
        v += __shfl_xor_sync(FULL, v, 2);
        v += __shfl_xor_sync(FULL, v, 1);
        vals[kk] = v;
    }
    if (lane == 0) {
        #pragma unroll
        for (int kk = 0; kk < 5; kk++) s_red[warp][kk] = vals[kk];
    }
    __syncthreads();

    if (warp == 0 && lane < 5) {
        float v = 0.0f;
        #pragma unroll
        for (int w = 0; w < NWARPS; w++) v += s_red[w][lane];
        atomicAdd(&g_acc[lane], (double)v);
    }
    __syncthreads();

    // ---- Last block finalizes and resets for next graph replay ----
    if (tid == 0) {
        __threadfence();
        const unsigned done = atomicAdd(&g_count, 1u);
        s_islast = (done == (unsigned)(gridDim.x - 1)) ? 1 : 0;
    }
    __syncthreads();

    if (s_islast && tid == 0) {
        const double a0 = atomicAdd(&g_acc[0], 0.0);
        const double a1 = atomicAdd(&g_acc[1], 0.0);
        const double a2 = atomicAdd(&g_acc[2], 0.0);
        const double a3 = atomicAdd(&g_acc[3], 0.0);
        const double npos = atomicAdd(&g_acc[4], 0.0);

        const double jsq = npos * (double)NA;
        const double qit = ((double)NCELLS - npos) * (double)NA;
        o[0] = (float)(a0 / jsq + a3 / (jsq + qit));
        o[1] = (float)(a1 / jsq);
        o[2] = (float)(a2 / jsq);

        g_acc[0] = 0.0; g_acc[1] = 0.0; g_acc[2] = 0.0;
        g_acc[3] = 0.0; g_acc[4] = 0.0;
        __threadfence();
        g_count = 0u;
    }
}

extern "C" void kernel_launch(void* const* d_in, const int* in_sizes, int n_in,
                              void* d_out, int out_size) {
    const float* out_t = (const float*)d_in[0];
    const float* target = (const float*)d_in[1];
    float* o = (float*)d_out;

    const int smem_bytes = NWARPS * 2 * CHUNK_FLOATS * (int)sizeof(float); // 23040
    static int configured = 0;
    if (!configured) {
        cudaFuncSetAttribute(loss_kernel,
                             cudaFuncAttributeMaxDynamicSharedMemorySize,
                             smem_bytes);
        configured = 1;
    }
    loss_kernel<<<NBLOCKS, TPB, smem_bytes>>>(out_t, target, o);
}

// round 6
// speedup vs baseline: 1.5512x; 1.1383x over previous
#include <cuda_runtime.h>
#include <math.h>

#define GXN 128
#define GYN 128
#define NA 9
#define NCELLS (32 * 128 * 128)          // 524288
#define TPB 128
#define NWARPS (TPB / 32)                // 4
#define CHUNK 16                          // cells per warp-chunk
#define CHUNKS 4                          // chunks per warp
#define WARP_CELLS (CHUNK * CHUNKS)       // 64
#define BLOCK_CELLS (WARP_CELLS * NWARPS) // 256
#define NBLOCKS (NCELLS / BLOCK_CELLS)    // 2048
#define CHUNK_FLOATS (CHUNK * 45)         // 720
#define CHUNK_F4 (CHUNK_FLOATS / 4)       // 180

__device__ double g_acc[5];
__device__ unsigned int g_count = 0;

__device__ __forceinline__ unsigned smem_u32(const void* p) {
    return (unsigned)__cvta_generic_to_shared(p);
}
#define CP_ASYNC_16(dst_u32, src_ptr) \
    asm volatile("cp.async.cg.shared.global [%0], [%1], 16;" :: "r"(dst_u32), "l"(src_ptr))
#define CP_COMMIT() asm volatile("cp.async.commit_group;")
#define CP_WAIT(n)  asm volatile("cp.async.wait_group %0;" :: "n"(n))

// Stage one 16-cell chunk (720 floats = 180 float4) with one warp.
__device__ __forceinline__ void stage_chunk(const float* __restrict__ out,
                                            int cellBase, float* buf, int lane)
{
    const float4* src = reinterpret_cast<const float4*>(out + (size_t)cellBase * 45);
    const unsigned dst = smem_u32(buf);
    #pragma unroll
    for (int r = 0; r < 5; r++) {
        const int idx = lane + r * 32;
        CP_ASYNC_16(dst + idx * 16, src + idx);
    }
    {
        const int idx = lane + 160;                 // 180 = 5*32 + 20
        if (idx < CHUNK_F4) CP_ASYNC_16(dst + idx * 16, src + idx);
    }
}

__global__ __launch_bounds__(TPB) void loss_kernel(
    const float* __restrict__ out,
    const float* __restrict__ target,
    float* __restrict__ o)
{
    extern __shared__ float s_buf[];      // NWARPS * 2 * 720 floats = 23040 B

    // Compacted per-pos-cell params: ax1, ax2, ay1, ay2, atana, zx, zy, cell-idx
    __shared__ float s_cellp[NWARPS][CHUNK][8];   // 2048 B
    __shared__ float s_red[NWARPS][5];
    __shared__ int s_islast;

    const int tid = threadIdx.x;
    const int warp = tid >> 5;
    const int lane = tid & 31;
    const unsigned FULL = 0xFFFFFFFFu;

    const int warpBase = blockIdx.x * BLOCK_CELLS + warp * WARP_CELLS;
    float* wbuf = s_buf + warp * (2 * CHUNK_FLOATS);

    // ---- Prologue: stage chunks 0,1; prefetch st5 of chunk 0 ----
    stage_chunk(out, warpBase + 0 * CHUNK, wbuf, lane);
    CP_COMMIT();
    stage_chunk(out, warpBase + 1 * CHUNK, wbuf + CHUNK_FLOATS, lane);
    CP_COMMIT();
    float st5_cur = 0.0f;
    if (lane < CHUNK)
        st5_cur = __ldg(target + (size_t)(warpBase + lane) * 18 + 5);

    float acc_allloss = 0.0f;
    float acc_jbb = 0.0f;
    float acc_huhuh = 0.0f;
    float acc_zsd = 0.0f;
    float acc_npos = 0.0f;

    const float FOUR_OVER_PI2 = 4.0f / (3.14159265358979323846f * 3.14159265358979323846f);

    #pragma unroll
    for (int k = 0; k < CHUNKS; k++) {
        const int chunkBase = warpBase + k * CHUNK;
        float* buf = wbuf + (k & 1) * CHUNK_FLOATS;

        // Prefetch next chunk's st5 before blocking on the copy
        float st5_next = 0.0f;
        if (k + 1 < CHUNKS && lane < CHUNK)
            st5_next = __ldg(target + (size_t)(chunkBase + CHUNK + lane) * 18 + 5);

        if (k == CHUNKS - 1) { CP_WAIT(0); } else { CP_WAIT(1); }
        __syncwarp();

        const bool provider_pos = (lane < CHUNK) && (st5_cur > 0.8f);
        const unsigned m = __ballot_sync(FULL, provider_pos) & 0xFFFFu;
        const int nP = __popc(m);

        // ---- Providers: per-pos-cell invariants into compacted slots ----
        if (provider_pos) {
            const int off = __popc(m & ((1u << lane) - 1u));
            const int cellc = chunkBase + lane;
            const int gy = cellc & 127;
            const int gx = (cellc >> 7) & 127;

            const float* st = target + (size_t)cellc * 18;
            const float st0 = __ldg(st + 0);
            const float st1 = __ldg(st + 1);
            const float st2 = __ldg(st + 2);
            const float st3 = __ldg(st + 3);

            const float ax1 = st0 - st2 * 0.5f;
            const float ax2 = st0 + st2 * 0.5f;
            const float ay1 = st1 - st3 * 0.5f;
            const float ay2 = st1 + st3 * 0.5f;
            const float atana = atanf(__fdividef(ax2 - ax1, ay2 - ay1));
            const float zx = (float)gx * (1.0f / GXN) + 1.0f / (2.0f * GXN);
            const float zy = (float)gy * (1.0f / GYN) + 1.0f / (2.0f * GYN);

            float* p = s_cellp[warp][off];
            p[0] = ax1; p[1] = ax2; p[2] = ay1; p[3] = ay2;
            p[4] = atana; p[5] = zx; p[6] = zy;
            p[7] = __int_as_float(lane);
            acc_npos += 1.0f;
        }

        // ---- Negative path: lane-pair per cell, half anchors each ----
        {
            const int c = lane & 15;
            const int half = lane >> 4;
            const bool cpos = (m >> c) & 1u;
            if (!cpos) {
                const float* s = buf + c * 45 + (half ? 25 : 0);
                #pragma unroll
                for (int j = 0; j < 5; j++) {
                    if (j < 4 || !half) {
                        const float obj = s[j * 5 + 4];
                        acc_zsd += obj * obj;
                    }
                }
            }
        }
        __syncwarp();   // providers' s_cellp visible

        // ---- Heavy path: nP*9 work items, 32 per pass ----
        const int items = nP * NA;
        for (int base2 = 0; base2 < items; base2 += 32) {
            const int i = base2 + lane;
            if (i < items) {
                const int r = i / 9;
                const int a = i - r * 9;
                const float* p = s_cellp[warp][r];
                const float ax1 = p[0], ax2 = p[1], ay1 = p[2], ay2 = p[3];
                const float atana = p[4], zx = p[5], zy = p[6];
                const int c = __float_as_int(p[7]);

                const float* s = buf + c * 45 + a * 5;
                const float o0 = s[0];
                const float o1 = s[1];
                const float o2 = s[2];
                const float o3 = s[3];
                const float obj = s[4];

                const float area_a = (ax2 - ax1) * (ay2 - ay1);
                const float acx = (ax1 + ax2) * 0.5f;
                const float acy = (ay1 + ay2) * 0.5f;

                const float bcx = o0 - 0.5f + zx;
                const float bcy = o1 - 0.5f + zy;
                const float bw  = o2 - 0.5f + (1.0f / GXN);
                const float bh  = o3 - 0.5f + (1.0f / GYN);
                const float bx1 = bcx - bw * 0.5f;
                const float bx2 = bcx + bw * 0.5f;
                const float by1 = bcy - bh * 0.5f;
                const float by2 = bcy + bh * 0.5f;

                const float iw = fminf(ax2, bx2) - fmaxf(ax1, bx1);
                const float ih = fminf(ay2, by2) - fmaxf(ay1, by1);
                const float cross = (iw > 0.0f && ih > 0.0f) ? iw * ih : 0.0f;
                const float area_b = (bx2 - bx1) * (by2 - by1);
                const float uni = area_a + area_b - cross;
                const float iou = __fdividef(cross, uni + 1e-6f);

                const float dx = bcx - acx;
                const float dy = bcy - acy;
                const float d2 = dx * dx + dy * dy;

                const float cw = fmaxf(ax2, bx2) - fminf(ax1, bx1);
                const float ch = fmaxf(ay2, by2) - fminf(ay1, by1);
                const float c2 = cw * cw + ch * ch;

                const float diou = iou - __fdividef(d2, c2);

                const float da = atana - atanf(__fdividef(bx2 - bx1, by2 - by1));
                const float v = FOUR_OVER_PI2 * da * da;
                const float alpha = __fdividef(v, 1.0f - iou + v);
                const float los = 1.0f - (diou - alpha * v);

                const float om = 1.0f - obj;
                acc_allloss += los + om;
                acc_jbb += iou;
                acc_huhuh += om;
                acc_zsd += om * om;
            }
        }
        __syncwarp();   // buffer free for reuse

        if (k + 2 < CHUNKS)
            stage_chunk(out, warpBase + (k + 2) * CHUNK, buf, lane);
        CP_COMMIT();

        st5_cur = st5_next;
    }

    // ---- Block reduction: 4 sums + pos count ----
    float vals[5];
    vals[0] = acc_allloss;
    vals[1] = acc_jbb;
    vals[2] = acc_huhuh;
    vals[3] = acc_zsd;
    vals[4] = acc_npos;

    #pragma unroll
    for (int kk = 0; kk < 5; kk++) {
        float v = vals[kk];
        v += __shfl_xor_sync(FULL, v, 16);
        v += __shfl_xor_sync(FULL, v, 8);
        v += __shfl_xor_sync(FULL, v, 4);
        v += __shfl_xor_sync(FULL, v, 2);
        v += __shfl_xor_sync(FULL, v, 1);
        vals[kk] = v;
    }
    if (lane == 0) {
        #pragma unroll
        for (int kk = 0; kk < 5; kk++) s_red[warp][kk] = vals[kk];
    }
    __syncthreads();

    if (warp == 0 && lane < 5) {
        float v = 0.0f;
        #pragma unroll
        for (int w = 0; w < NWARPS; w++) v += s_red[w][lane];
        atomicAdd(&g_acc[lane], (double)v);
    }
    __syncthreads();

    // ---- Last block finalizes and resets for next graph replay ----
    if (tid == 0) {
        __threadfence();
        const unsigned done = atomicAdd(&g_count, 1u);
        s_islast = (done == (unsigned)(gridDim.x - 1)) ? 1 : 0;
    }
    __syncthreads();

    if (s_islast && tid == 0) {
        const double a0 = atomicAdd(&g_acc[0], 0.0);
        const double a1 = atomicAdd(&g_acc[1], 0.0);
        const double a2 = atomicAdd(&g_acc[2], 0.0);
        const double a3 = atomicAdd(&g_acc[3], 0.0);
        const double npos = atomicAdd(&g_acc[4], 0.0);

        const double jsq = npos * (double)NA;
        const double qit = ((double)NCELLS - npos) * (double)NA;
        o[0] = (float)(a0 / jsq + a3 / (jsq + qit));
        o[1] = (float)(a1 / jsq);
        o[2] = (float)(a2 / jsq);

        g_acc[0] = 0.0; g_acc[1] = 0.0; g_acc[2] = 0.0;
        g_acc[3] = 0.0; g_acc[4] = 0.0;
        __threadfence();
        g_count = 0u;
    }
}

extern "C" void kernel_launch(void* const* d_in, const int* in_sizes, int n_in,
                              void* d_out, int out_size) {
    const float* out_t = (const float*)d_in[0];
    const float* target = (const float*)d_in[1];
    float* o = (float*)d_out;

    const int smem_bytes = NWARPS * 2 * CHUNK_FLOATS * (int)sizeof(float); // 23040
    static int configured = 0;
    if (!configured) {
        cudaFuncSetAttribute(loss_kernel,
                             cudaFuncAttributeMaxDynamicSharedMemorySize,
                             smem_bytes);
        configured = 1;
    }
    loss_kernel<<<NBLOCKS, TPB, smem_bytes>>>(out_t, target, o);
}